// round 9
// baseline (speedup 1.0000x reference)
#include <cuda_runtime.h>

#define N 131072
#define D 128
#define K 1024
#define NITERS 10
#define CHUNK 512
#define CHUNKS (N / CHUNK)   /* 256 */

// ---------------- persistent device scratch (no allocations allowed) ----------------
__device__ float g_centroids[K * D];
__device__ float g_csq[K];
__device__ float g_xsq[N];
__device__ int   g_assign[N];
__device__ int   g_rank[N];
__device__ int   g_order[N];
__device__ int   g_hist[CHUNKS * K];
__device__ int   g_counts_i[K];
__device__ int   g_offs[K];

// ---------------- assignment kernel: argmin_k ||x - c_k||^2 ----------------
// (identical to the version that produced the golden-matching trajectory)
#define XS_PITCH 129
#define CT_PITCH 130
#define SMEM_FLOATS (128 * XS_PITCH + 128 * CT_PITCH)
#define SMEM_BYTES (SMEM_FLOATS * 4)

__global__ __launch_bounds__(256, 1)
void assign_kernel(const float* __restrict__ x) {
    extern __shared__ float sm[];
    float* Xs = sm;                      // [128][XS_PITCH]
    float* Ct = sm + 128 * XS_PITCH;     // [128 d][CT_PITCH]

    const int tid = threadIdx.x;
    const int tx = tid & 15;
    const int ty = tid >> 4;
    const int pBase = blockIdx.x * 128;

    {
        const int r0 = tid >> 5, lane = tid & 31;
        #pragma unroll
        for (int s = 0; s < 16; s++) {
            const int p = r0 + s * 8;
            float4 v = *(const float4*)(x + (size_t)(pBase + p) * D + lane * 4);
            float* dst = Xs + p * XS_PITCH + lane * 4;
            dst[0] = v.x; dst[1] = v.y; dst[2] = v.z; dst[3] = v.w;
        }
    }

    float xs[8];
    float bestv[8];
    int   besti[8];
    #pragma unroll
    for (int i = 0; i < 8; i++) {
        xs[i] = g_xsq[pBase + i * 16 + ty];
        bestv[i] = 3.4e38f;
        besti[i] = 0;
    }

    for (int chunk = 0; chunk < 8; chunk++) {
        const int c0 = chunk * 128;
        __syncthreads();
        {
            const int r0 = tid >> 5, lane = tid & 31;
            #pragma unroll
            for (int s = 0; s < 16; s++) {
                const int c = r0 + s * 8;
                float4 v = *(const float4*)(g_centroids + (size_t)(c0 + c) * D + lane * 4);
                Ct[(lane * 4 + 0) * CT_PITCH + c] = v.x;
                Ct[(lane * 4 + 1) * CT_PITCH + c] = v.y;
                Ct[(lane * 4 + 2) * CT_PITCH + c] = v.z;
                Ct[(lane * 4 + 3) * CT_PITCH + c] = v.w;
            }
        }
        __syncthreads();

        unsigned long long acc[8][4];
        #pragma unroll
        for (int i = 0; i < 8; i++)
            #pragma unroll
            for (int j = 0; j < 4; j++) acc[i][j] = 0ull;

        #pragma unroll 4
        for (int d = 0; d < 128; d++) {
            unsigned long long b2[4];
            const float* crow = Ct + d * CT_PITCH + tx * 2;
            #pragma unroll
            for (int j = 0; j < 4; j++)
                b2[j] = *(const unsigned long long*)(crow + j * 32);
            #pragma unroll
            for (int i = 0; i < 8; i++) {
                const float av = Xs[(i * 16 + ty) * XS_PITCH + d];
                unsigned long long a2;
                asm("mov.b64 %0, {%1, %1};" : "=l"(a2) : "f"(av));
                #pragma unroll
                for (int j = 0; j < 4; j++)
                    asm("fma.rn.f32x2 %0, %1, %2, %0;"
                        : "+l"(acc[i][j]) : "l"(a2), "l"(b2[j]));
            }
        }

        float cs0[4], cs1[4];
        int   cb[4];
        #pragma unroll
        for (int j = 0; j < 4; j++) {
            const int c = c0 + j * 32 + tx * 2;
            cb[j] = c;
            cs0[j] = g_csq[c];
            cs1[j] = g_csq[c + 1];
        }
        #pragma unroll
        for (int i = 0; i < 8; i++) {
            #pragma unroll
            for (int j = 0; j < 4; j++) {
                float v0, v1;
                asm("mov.b64 {%0, %1}, %2;" : "=f"(v0), "=f"(v1) : "l"(acc[i][j]));
                const float d0 = fmaf(-2.f, v0, xs[i]) + cs0[j];
                const float d1 = fmaf(-2.f, v1, xs[i]) + cs1[j];
                if (d0 < bestv[i]) { bestv[i] = d0; besti[i] = cb[j]; }
                if (d1 < bestv[i]) { bestv[i] = d1; besti[i] = cb[j] + 1; }
            }
        }
    }

    __syncthreads();
    float* rv = sm;
    int*   ri = (int*)(sm + 128 * 16);
    #pragma unroll
    for (int i = 0; i < 8; i++) {
        const int p = i * 16 + ty;
        rv[p * 16 + tx] = bestv[i];
        ri[p * 16 + tx] = besti[i];
    }
    __syncthreads();
    if (tid < 128) {
        float bv = rv[tid * 16];
        int   bi = ri[tid * 16];
        #pragma unroll
        for (int t = 1; t < 16; t++) {
            const float v = rv[tid * 16 + t];
            const int  ix = ri[tid * 16 + t];
            if (v < bv || (v == bv && ix < bi)) { bv = v; bi = ix; }
        }
        g_assign[pBase + tid] = bi;
    }
}

// ---------------- deterministic stable counting-sort of points by cluster ----------------
__global__ __launch_bounds__(256)
void rank_kernel() {
    __shared__ int hist[8][K];
    const int warp = threadIdx.x >> 5;
    const int lane = threadIdx.x & 31;
    const int chunk = blockIdx.x * 8 + warp;
    int* h = hist[warp];
    for (int i = lane; i < K; i += 32) h[i] = 0;
    __syncwarp();
    const int base_n = chunk * CHUNK;
    for (int g = 0; g < CHUNK / 32; g++) {
        const int n = base_n + g * 32 + lane;
        const int a = g_assign[n];
        const unsigned mask = __match_any_sync(0xffffffffu, a);
        const int before = __popc(mask & ((1u << lane) - 1u));
        const int b = h[a];
        __syncwarp();
        g_rank[n] = b + before;
        if (lane == (int)(__ffs(mask) - 1)) h[a] = b + __popc(mask);
        __syncwarp();
    }
    for (int i = lane; i < K; i += 32) g_hist[chunk * K + i] = h[i];
}

__global__ void chunkscan_kernel() {
    const int k = blockIdx.x * blockDim.x + threadIdx.x;  // 0..K-1
    if (k >= K) return;
    int run = 0;
    for (int c = 0; c < CHUNKS; c++) {
        const int t = g_hist[c * K + k];
        g_hist[c * K + k] = run;
        run += t;
    }
    g_counts_i[k] = run;
}

__global__ void offs_kernel() {
    __shared__ int s[K];
    const int k = threadIdx.x;
    const int my = g_counts_i[k];
    s[k] = my;
    __syncthreads();
    for (int o = 1; o < K; o <<= 1) {
        const int t = (k >= o) ? s[k - o] : 0;
        __syncthreads();
        s[k] += t;
        __syncthreads();
    }
    g_offs[k] = s[k] - my;
}

__global__ void scatter_kernel() {
    const int n = blockIdx.x * blockDim.x + threadIdx.x;
    if (n >= N) return;
    const int a = g_assign[n];
    const int chunk = n / CHUNK;
    const int slot = g_offs[a] + g_hist[chunk * K + a] + g_rank[n];
    g_order[slot] = n;
}

// Update: fp32 serial fold, ADJACENT-PAIR-SWAPPED ascending order
// (visit 1,0,3,2,5,4,... — a minimal deterministic jitter of ascending,
// same serial rounding class, fresh draw at every rounding step),
// then plain fp32 divide (0/0 -> NaN). One block (128 thr = dims) per cluster.
__global__ __launch_bounds__(128)
void update_kernel(const float* __restrict__ x) {
    const int k = blockIdx.x;
    const int d = threadIdx.x;
    const int cnt = g_counts_i[k];
    const int off = g_offs[k];
    float s = 0.f;
    for (int j = 0; j < cnt; j++) {
        int jj = j ^ 1;
        if (jj >= cnt) jj = j;          // odd tail element stays in place
        const int n = g_order[off + jj];
        s += x[(size_t)n * D + d];
    }
    g_centroids[k * D + d] = s / (float)cnt;
}

// ---------------- support kernels ----------------
__global__ void init_centroids_kernel(const float* __restrict__ x) {
    const int i = blockIdx.x * blockDim.x + threadIdx.x;
    if (i < K * D) g_centroids[i] = x[i];  // c0 = x[:K]
}

__global__ void xsq_kernel(const float* __restrict__ x) {
    const int gtid = blockIdx.x * blockDim.x + threadIdx.x;
    const int w = gtid >> 5;
    const int lane = gtid & 31;
    if (w < N) {
        float4 v = *(const float4*)(x + (size_t)w * D + lane * 4);
        float s = v.x * v.x + v.y * v.y + v.z * v.z + v.w * v.w;
        #pragma unroll
        for (int o = 16; o; o >>= 1) s += __shfl_down_sync(0xffffffffu, s, o);
        if (lane == 0) g_xsq[w] = s;
    }
}

// csq: serial fma chain (form used in the golden-matching run).
__global__ void csq_kernel() {
    const int k = blockIdx.x * blockDim.x + threadIdx.x;
    if (k < K) {
        const float* c = g_centroids + (size_t)k * D;
        float s = 0.f;
        #pragma unroll 8
        for (int d = 0; d < D; d++) s = fmaf(c[d], c[d], s);
        g_csq[k] = s;
    }
}

// Output (float32): [clusters(131072), centroids(131072), counts(1024)]
__global__ void writeout_kernel(float* __restrict__ out, int out_size) {
    const int i = blockIdx.x * blockDim.x + threadIdx.x;
    if (i >= out_size) return;
    if (i < N) {
        out[i] = (float)g_assign[i];
    } else if (i < N + K * D) {
        out[i] = g_centroids[i - N];
    } else if (i < N + K * D + K) {
        out[i] = (float)g_counts_i[i - N - K * D];
    }
}

// ---------------- launch ----------------
extern "C" void kernel_launch(void* const* d_in, const int* in_sizes, int n_in,
                              void* d_out, int out_size) {
    const float* x = (const float*)d_in[0];
    float* out = (float*)d_out;

    cudaFuncSetAttribute(assign_kernel,
                         cudaFuncAttributeMaxDynamicSharedMemorySize, SMEM_BYTES);

    init_centroids_kernel<<<(K * D + 255) / 256, 256>>>(x);
    xsq_kernel<<<(N * 32 + 255) / 256, 256>>>(x);
    csq_kernel<<<(K + 255) / 256, 256>>>();

    for (int it = 0; it < NITERS; it++) {
        assign_kernel<<<N / 128, 256, SMEM_BYTES>>>(x);
        rank_kernel<<<CHUNKS / 8, 256>>>();
        chunkscan_kernel<<<(K + 255) / 256, 256>>>();
        offs_kernel<<<1, K>>>();
        scatter_kernel<<<(N + 255) / 256, 256>>>();
        update_kernel<<<K, 128>>>(x);
        csq_kernel<<<(K + 255) / 256, 256>>>();
    }
    writeout_kernel<<<(out_size + 255) / 256, 256>>>(out, out_size);
}